// round 3
// baseline (speedup 1.0000x reference)
#include <cuda_runtime.h>
#include <math.h>

#define BB 32
#define TT 1024
#define VV 128
#define EE 512
#define HH 1024
#define GG 3072

#define NC 128           // persistent CTAs (<= 148 SMs, 1 CTA/SM)
#define RT 256           // threads per recurrence CTA
// SMEM: Usm 1024*8*float4 = 131072 ; Gsm 128*24*4 = 12288 ; red 6*128*4 = 3072
#define SMEM_RECUR (131072 + 12288 + 3072)

// ------------------------- device scratch (no mallocs) -----------------------
__device__ float    d_G[(size_t)VV * GG];            // input gates per vocab id
__device__ float    d_hbuf[2 * HH * BB];             // double-buffered h, [buf][k][b]
__device__ float    d_hs[(size_t)TT * BB * HH];      // hidden states [t][b][h]
__device__ int      d_tokT[TT * BB];                 // transposed tokens [t][b]
__device__ unsigned d_bar;                           // grid barrier counter

// ------------------------------- helpers -------------------------------------
__device__ __forceinline__ float sigmoidf_(float x) { return 1.0f / (1.0f + expf(-x)); }

__device__ __forceinline__ void gridbar(unsigned target) {
    __threadfence();              // order this thread's global writes
    __syncthreads();              // whole CTA done with this step
    if (threadIdx.x == 0) {
        atomicAdd(&d_bar, 1u);
        while (*((volatile unsigned*)&d_bar) < target) { }
        __threadfence();
    }
    __syncthreads();
}

// ---------------- k_gin: G[v,g] = emb[v]@Wk + b_in ; reset barrier -----------
__global__ void k_gin(const float* __restrict__ emb,
                      const float* __restrict__ Wk,
                      const float* __restrict__ b_in) {
    if (blockIdx.x == 0 && blockIdx.y == 0 && threadIdx.x == 0) d_bar = 0u;

    __shared__ float esm[8][EE];
    const int g  = blockIdx.x * 128 + threadIdx.x;   // 0..3071
    const int v0 = blockIdx.y * 8;

    for (int i = threadIdx.x; i < 8 * EE; i += 128)
        esm[i >> 9][i & (EE - 1)] = emb[(size_t)v0 * EE + i];
    __syncthreads();

    float acc[8];
    const float bi = b_in[g];
#pragma unroll
    for (int i = 0; i < 8; i++) acc[i] = bi;

    for (int e = 0; e < EE; e++) {
        float w = Wk[(size_t)e * GG + g];
#pragma unroll
        for (int i = 0; i < 8; i++) acc[i] = fmaf(esm[i][e], w, acc[i]);
    }
#pragma unroll
    for (int i = 0; i < 8; i++) d_G[(size_t)(v0 + i) * GG + g] = acc[i];
}

// ---------------- k_init: transpose tokens, zero h buffer 0 ------------------
__global__ void k_init(const int* __restrict__ tokens) {
    int b = blockIdx.x, t = threadIdx.x;
    d_tokT[t * BB + b] = tokens[b * TT + t];
    d_hbuf[b * TT + t] = 0.0f;       // covers exactly HH*BB = 32768 floats (buf 0)
}

// ---------------- k_recur: persistent GRU scan (pure scalar fp32) ------------
__global__ void __launch_bounds__(RT, 1)
k_recur(const float* __restrict__ Uk, const float* __restrict__ b_rec) {
    extern __shared__ char sm_[];
    float4* Usm = (float4*)sm_;                       // [k*8+col] = {uz, ur, uh, 0}
    float*  Gsm = (float*)(sm_ + 131072);             // [v*24 + col*3 + gate]
    float*  red = (float*)(sm_ + 131072 + 12288);     // [6][128]

    const int tid   = threadIdx.x;
    const int cta   = blockIdx.x;
    const int half  = tid >> 7;        // k-split: 0 -> [0,512), 1 -> [512,1024)
    const int lt    = tid & 127;
    const int bp    = lt >> 3;         // batch pair 0..15
    const int col   = lt & 7;          // local column 0..7
    const int b0    = bp * 2;
    const int j     = cta * 8 + col;   // global hidden column
    const int kbase = half * 512;

    // one-time SMEM fills
    for (int idx = tid; idx < 8192; idx += RT) {
        int k = idx >> 3, cc = idx & 7, jj = cta * 8 + cc;
        Usm[idx] = make_float4(Uk[(size_t)k * GG + jj],
                               Uk[(size_t)k * GG + HH + jj],
                               Uk[(size_t)k * GG + 2 * HH + jj],
                               0.0f);
    }
    for (int idx = tid; idx < VV * 8; idx += RT) {
        int v = idx >> 3, cc = idx & 7, jj = cta * 8 + cc;
        Gsm[v * 24 + cc * 3 + 0] = d_G[(size_t)v * GG + jj];
        Gsm[v * 24 + cc * 3 + 1] = d_G[(size_t)v * GG + HH + jj];
        Gsm[v * 24 + cc * 3 + 2] = d_G[(size_t)v * GG + 2 * HH + jj];
    }
    const float brz = b_rec[j];
    const float brr = b_rec[HH + j];
    const float brh = b_rec[2 * HH + j];
    __syncthreads();

    float h0 = 0.0f, h1 = 0.0f;       // this thread's own h (half 0 only)

    for (int t = 0; t < TT; ++t) {
        const int rb = t & 1, wb = rb ^ 1;
        const float2* hsrc2 = (const float2*)(d_hbuf + rb * (HH * BB));

        float az0 = 0.f, ar0 = 0.f, ah0 = 0.f;
        float az1 = 0.f, ar1 = 0.f, ah1 = 0.f;

#pragma unroll 8
        for (int kk = 0; kk < 512; ++kk) {
            int k = kbase + kk;
            float2 h2 = __ldcg(hsrc2 + k * 16 + bp);    // h[k][b0], h[k][b0+1]
            float4 u  = Usm[(k << 3) + col];            // {uz, ur, uh, _}
            az0 = fmaf(h2.x, u.x, az0);
            ar0 = fmaf(h2.x, u.y, ar0);
            ah0 = fmaf(h2.x, u.z, ah0);
            az1 = fmaf(h2.y, u.x, az1);
            ar1 = fmaf(h2.y, u.y, ar1);
            ah1 = fmaf(h2.y, u.z, ah1);
        }

        if (half == 1) {
            red[0 * 128 + lt] = az0;
            red[1 * 128 + lt] = ar0;
            red[2 * 128 + lt] = ah0;
            red[3 * 128 + lt] = az1;
            red[4 * 128 + lt] = ar1;
            red[5 * 128 + lt] = ah1;
        }
        __syncthreads();

        if (half == 0) {
            az0 += red[0 * 128 + lt];
            ar0 += red[1 * 128 + lt];
            ah0 += red[2 * 128 + lt];
            az1 += red[3 * 128 + lt];
            ar1 += red[4 * 128 + lt];
            ah1 += red[5 * 128 + lt];

            int tk0 = d_tokT[t * BB + b0];
            int tk1 = d_tokT[t * BB + b0 + 1];
            const float* g0 = &Gsm[tk0 * 24 + col * 3];
            const float* g1 = &Gsm[tk1 * 24 + col * 3];

            // Keras gate order (z, r, h), reset_after=True
            float z  = sigmoidf_(g0[0] + az0 + brz);
            float r  = sigmoidf_(g0[1] + ar0 + brr);
            float hc = tanhf(g0[2] + r * (ah0 + brh));
            float n0 = z * h0 + (1.0f - z) * hc;

            z  = sigmoidf_(g1[0] + az1 + brz);
            r  = sigmoidf_(g1[1] + ar1 + brr);
            hc = tanhf(g1[2] + r * (ah1 + brh));
            float n1 = z * h1 + (1.0f - z) * hc;

            h0 = n0; h1 = n1;
            __stcg((float2*)(d_hbuf + wb * (HH * BB) + j * BB + b0),
                   make_float2(n0, n1));
            d_hs[((size_t)t * BB + b0) * HH + j]     = n0;
            d_hs[((size_t)t * BB + b0 + 1) * HH + j] = n1;
        }

        gridbar((unsigned)NC * (unsigned)(t + 1));
    }
}

// ---------------- k_logits: out[b,t,:] = hs[t,b,:]@Wd + bd -------------------
__global__ void __launch_bounds__(256)
k_logits(const float* __restrict__ Wd, const float* __restrict__ bd,
         float* __restrict__ out) {
    __shared__ float Asm[32 * 68];    // [m][k], padded rows
    __shared__ float Bsm[64 * 128];   // [k][v]

    const int t   = blockIdx.x;
    const int tid = threadIdx.x;
    const int m0  = (tid >> 4) * 2;   // 2 rows per thread
    const int n0  = (tid & 15) * 8;   // 8 cols per thread

    float acc[2][8];
#pragma unroll
    for (int a = 0; a < 2; a++)
#pragma unroll
        for (int q = 0; q < 8; q++) acc[a][q] = 0.0f;

    for (int k0 = 0; k0 < HH; k0 += 64) {
        __syncthreads();
#pragma unroll
        for (int i = 0; i < 2; i++) {
            int fidx = i * 256 + tid;            // 512 float4s of A
            int m = fidx >> 4, k4 = fidx & 15;
            float4 vA = *reinterpret_cast<const float4*>(
                &d_hs[((size_t)t * BB + m) * HH + k0 + k4 * 4]);
            *reinterpret_cast<float4*>(&Asm[m * 68 + k4 * 4]) = vA;
        }
#pragma unroll
        for (int i = 0; i < 8; i++) {
            int fidx = i * 256 + tid;            // 2048 float4s of B
            int kk = fidx >> 5, v4 = fidx & 31;
            float4 vB = *reinterpret_cast<const float4*>(
                &Wd[(size_t)(k0 + kk) * VV + v4 * 4]);
            *reinterpret_cast<float4*>(&Bsm[kk * 128 + v4 * 4]) = vB;
        }
        __syncthreads();

#pragma unroll 4
        for (int kk = 0; kk < 64; ++kk) {
            float a0 = Asm[m0 * 68 + kk];
            float a1 = Asm[(m0 + 1) * 68 + kk];
            float4 q0 = *reinterpret_cast<const float4*>(&Bsm[kk * 128 + n0]);
            float4 q1 = *reinterpret_cast<const float4*>(&Bsm[kk * 128 + n0 + 4]);
            acc[0][0] = fmaf(a0, q0.x, acc[0][0]);
            acc[0][1] = fmaf(a0, q0.y, acc[0][1]);
            acc[0][2] = fmaf(a0, q0.z, acc[0][2]);
            acc[0][3] = fmaf(a0, q0.w, acc[0][3]);
            acc[0][4] = fmaf(a0, q1.x, acc[0][4]);
            acc[0][5] = fmaf(a0, q1.y, acc[0][5]);
            acc[0][6] = fmaf(a0, q1.z, acc[0][6]);
            acc[0][7] = fmaf(a0, q1.w, acc[0][7]);
            acc[1][0] = fmaf(a1, q0.x, acc[1][0]);
            acc[1][1] = fmaf(a1, q0.y, acc[1][1]);
            acc[1][2] = fmaf(a1, q0.z, acc[1][2]);
            acc[1][3] = fmaf(a1, q0.w, acc[1][3]);
            acc[1][4] = fmaf(a1, q1.x, acc[1][4]);
            acc[1][5] = fmaf(a1, q1.y, acc[1][5]);
            acc[1][6] = fmaf(a1, q1.z, acc[1][6]);
            acc[1][7] = fmaf(a1, q1.w, acc[1][7]);
        }
    }

#pragma unroll
    for (int a = 0; a < 2; a++) {
        int m = m0 + a;
        float* op = &out[((size_t)m * TT + t) * VV + n0];
#pragma unroll
        for (int q = 0; q < 8; q++) op[q] = acc[a][q] + bd[n0 + q];
    }
}

// ------------------------------- launch --------------------------------------
extern "C" void kernel_launch(void* const* d_in, const int* in_sizes, int n_in,
                              void* d_out, int out_size) {
    (void)in_sizes; (void)n_in; (void)out_size;
    const int*   tokens = (const int*)  d_in[0];
    const float* emb    = (const float*)d_in[1];
    const float* Wk     = (const float*)d_in[2];
    const float* Uk     = (const float*)d_in[3];
    const float* b_in   = (const float*)d_in[4];
    const float* b_rec  = (const float*)d_in[5];
    const float* Wd     = (const float*)d_in[6];
    const float* bd     = (const float*)d_in[7];
    float* out = (float*)d_out;

    cudaFuncSetAttribute(k_recur, cudaFuncAttributeMaxDynamicSharedMemorySize, SMEM_RECUR);

    dim3 gin_grid(GG / 128, VV / 8);
    k_gin<<<gin_grid, 128>>>(emb, Wk, b_in);
    k_init<<<BB, TT>>>(tokens);
    k_recur<<<NC, RT, SMEM_RECUR>>>(Uk, b_rec);
    k_logits<<<TT, 256>>>(Wd, bd, out);
}

// round 4
// speedup vs baseline: 1.0941x; 1.0941x over previous
#include <cuda_runtime.h>
#include <math.h>

#define BB 32
#define TT 1024
#define VV 128
#define EE 512
#define HH 1024
#define GG 3072

#define NC 128           // persistent CTAs (1 per SM)
#define RT 512           // threads per recurrence CTA (16 warps, split-K-4)
// SMEM: U4 8192*16=131072 ; U2 8192*8=65536 ; Gsm 128*24*4=12288 ; red 9*128*8=9216
#define SMEM_RECUR (131072 + 65536 + 12288 + 9216)

// ------------------------- device scratch (no mallocs) -----------------------
__device__ float    d_G[(size_t)VV * GG];            // input gates per vocab id
__device__ float    d_hbuf[2 * HH * BB];             // double-buffered h, [buf][k][b]
__device__ float    d_hs[(size_t)TT * BB * HH];      // hidden states [t][b][h]
__device__ int      d_tokT[TT * BB];                 // transposed tokens [t][b]
__device__ unsigned d_bar;                           // grid barrier counter

// ------------------------------- helpers -------------------------------------
typedef unsigned long long ull;

__device__ __forceinline__ void fma2(ull& acc, ull a, ull b) {
    asm("fma.rn.f32x2 %0, %1, %2, %0;" : "+l"(acc) : "l"(a), "l"(b));
}
__device__ __forceinline__ void add2(ull& acc, ull a) {
    asm("add.rn.f32x2 %0, %1, %0;" : "+l"(acc) : "l"(a));
}
__device__ __forceinline__ float2 unpack2(ull v) {
    float2 f;
    asm("mov.b64 {%0, %1}, %2;" : "=f"(f.x), "=f"(f.y) : "l"(v));
    return f;
}
__device__ __forceinline__ float sigmoidf_(float x) { return 1.0f / (1.0f + expf(-x)); }

__device__ __forceinline__ void gridbar(unsigned target) {
    __threadfence();              // ALL threads release their global writes
    __syncthreads();
    if (threadIdx.x == 0) {
        atomicAdd(&d_bar, 1u);
        while (*((volatile unsigned*)&d_bar) < target) { }
        __threadfence();
    }
    __syncthreads();
}

// ---------------- k_gin: G[v,g] = emb[v]@Wk + b_in ; reset barrier -----------
__global__ void k_gin(const float* __restrict__ emb,
                      const float* __restrict__ Wk,
                      const float* __restrict__ b_in) {
    if (blockIdx.x == 0 && blockIdx.y == 0 && threadIdx.x == 0) d_bar = 0u;

    __shared__ float esm[8][EE];
    const int g  = blockIdx.x * 128 + threadIdx.x;   // 0..3071
    const int v0 = blockIdx.y * 8;

    for (int i = threadIdx.x; i < 8 * EE; i += 128)
        esm[i >> 9][i & (EE - 1)] = emb[(size_t)v0 * EE + i];
    __syncthreads();

    float acc[8];
    const float bi = b_in[g];
#pragma unroll
    for (int i = 0; i < 8; i++) acc[i] = bi;

    for (int e = 0; e < EE; e++) {
        float w = Wk[(size_t)e * GG + g];
#pragma unroll
        for (int i = 0; i < 8; i++) acc[i] = fmaf(esm[i][e], w, acc[i]);
    }
#pragma unroll
    for (int i = 0; i < 8; i++) d_G[(size_t)(v0 + i) * GG + g] = acc[i];
}

// ---------------- k_init: transpose tokens, zero h buffer 0 ------------------
__global__ void k_init(const int* __restrict__ tokens) {
    int b = blockIdx.x, t = threadIdx.x;
    d_tokT[t * BB + b] = tokens[b * TT + t];
    d_hbuf[b * TT + t] = 0.0f;       // covers exactly HH*BB = 32768 floats (buf 0)
}

// ---------------- k_recur: persistent GRU scan (f32x2, split-K-4) ------------
__global__ void __launch_bounds__(RT, 1)
k_recur(const float* __restrict__ Uk, const float* __restrict__ b_rec) {
    extern __shared__ char sm_[];
    float4* U4  = (float4*)sm_;                         // [k*8+col] {uz,uz,ur,ur}
    float2* U2  = (float2*)(sm_ + 131072);              // [k*8+col] {uh,uh}
    float*  Gsm = (float*)(sm_ + 131072 + 65536);       // [v*24 + col*3 + gate]
    ull*    red = (ull*)(sm_ + 131072 + 65536 + 12288); // [3 quarters][3 gates][128]

    const int tid   = threadIdx.x;
    const int cta   = blockIdx.x;
    const int q     = tid >> 7;        // k-split quarter 0..3
    const int lt    = tid & 127;
    const int bp    = lt >> 3;         // batch pair 0..15
    const int col   = lt & 7;          // local column 0..7
    const int b0    = bp * 2;
    const int j     = cta * 8 + col;   // global hidden column
    const int kbase = q * 256;

    // one-time SMEM fills
    for (int idx = tid; idx < 8192; idx += RT) {
        int k = idx >> 3, cc = idx & 7, jj = cta * 8 + cc;
        float uz = Uk[(size_t)k * GG + jj];
        float ur = Uk[(size_t)k * GG + HH + jj];
        float uh = Uk[(size_t)k * GG + 2 * HH + jj];
        U4[idx] = make_float4(uz, uz, ur, ur);
        U2[idx] = make_float2(uh, uh);
    }
    for (int idx = tid; idx < VV * 8; idx += RT) {
        int v = idx >> 3, cc = idx & 7, jj = cta * 8 + cc;
        Gsm[v * 24 + cc * 3 + 0] = d_G[(size_t)v * GG + jj];
        Gsm[v * 24 + cc * 3 + 1] = d_G[(size_t)v * GG + HH + jj];
        Gsm[v * 24 + cc * 3 + 2] = d_G[(size_t)v * GG + 2 * HH + jj];
    }
    const float brz = b_rec[j];
    const float brr = b_rec[HH + j];
    const float brh = b_rec[2 * HH + j];
    __syncthreads();

    float h0 = 0.0f, h1 = 0.0f;       // this thread's own h (quarter 0 only)

    for (int t = 0; t < TT; ++t) {
        const int rb = t & 1, wb = rb ^ 1;
        const float* hsrc = d_hbuf + rb * (HH * BB);

        ull az = 0ull, ar = 0ull, ah = 0ull;

#pragma unroll 8
        for (int kk = 0; kk < 256; ++kk) {
            int k = kbase + kk;
            ull h2 = __ldcg((const ull*)(hsrc + k * BB + b0));           // {h[k][b0], h[k][b0+1]}
            ulonglong2 uzr = *reinterpret_cast<const ulonglong2*>(&U4[(k << 3) + col]);
            ull uh = *reinterpret_cast<const ull*>(&U2[(k << 3) + col]);
            fma2(az, h2, uzr.x);
            fma2(ar, h2, uzr.y);
            fma2(ah, h2, uh);
        }

        if (q != 0) {
            ull* rp = red + (size_t)(q - 1) * 384;
            rp[0 * 128 + lt] = az;
            rp[1 * 128 + lt] = ar;
            rp[2 * 128 + lt] = ah;
        }
        __syncthreads();

        if (q == 0) {
#pragma unroll
            for (int p = 0; p < 3; ++p) {
                const ull* rp = red + (size_t)p * 384;
                add2(az, rp[0 * 128 + lt]);
                add2(ar, rp[1 * 128 + lt]);
                add2(ah, rp[2 * 128 + lt]);
            }
            float2 fz = unpack2(az), fr = unpack2(ar), fh = unpack2(ah);

            int tk0 = d_tokT[t * BB + b0];
            int tk1 = d_tokT[t * BB + b0 + 1];
            const float* g0 = &Gsm[tk0 * 24 + col * 3];
            const float* g1 = &Gsm[tk1 * 24 + col * 3];

            // Keras gate order (z, r, h), reset_after=True
            float z  = sigmoidf_(g0[0] + fz.x + brz);
            float r  = sigmoidf_(g0[1] + fr.x + brr);
            float hc = tanhf(g0[2] + r * (fh.x + brh));
            float n0 = z * h0 + (1.0f - z) * hc;

            z  = sigmoidf_(g1[0] + fz.y + brz);
            r  = sigmoidf_(g1[1] + fr.y + brr);
            hc = tanhf(g1[2] + r * (fh.y + brh));
            float n1 = z * h1 + (1.0f - z) * hc;

            h0 = n0; h1 = n1;
            __stcg((float2*)(d_hbuf + wb * (HH * BB) + j * BB + b0),
                   make_float2(n0, n1));
            d_hs[((size_t)t * BB + b0) * HH + j]     = n0;
            d_hs[((size_t)t * BB + b0 + 1) * HH + j] = n1;
        }

        gridbar((unsigned)NC * (unsigned)(t + 1));
    }
}

// ---------------- k_logits: out[b,t,:] = hs[t,b,:]@Wd + bd -------------------
__global__ void __launch_bounds__(256)
k_logits(const float* __restrict__ Wd, const float* __restrict__ bd,
         float* __restrict__ out) {
    __shared__ float Asm[32 * 68];    // [m][k], padded rows
    __shared__ float Bsm[64 * 128];   // [k][v]

    const int t   = blockIdx.x;
    const int tid = threadIdx.x;
    const int m0  = (tid >> 4) * 2;   // 2 rows per thread
    const int n0  = (tid & 15) * 8;   // 8 cols per thread

    float acc[2][8];
#pragma unroll
    for (int a = 0; a < 2; a++)
#pragma unroll
        for (int q = 0; q < 8; q++) acc[a][q] = 0.0f;

    for (int k0 = 0; k0 < HH; k0 += 64) {
        __syncthreads();
#pragma unroll
        for (int i = 0; i < 2; i++) {
            int fidx = i * 256 + tid;            // 512 float4s of A
            int m = fidx >> 4, k4 = fidx & 15;
            float4 vA = *reinterpret_cast<const float4*>(
                &d_hs[((size_t)t * BB + m) * HH + k0 + k4 * 4]);
            *reinterpret_cast<float4*>(&Asm[m * 68 + k4 * 4]) = vA;
        }
#pragma unroll
        for (int i = 0; i < 8; i++) {
            int fidx = i * 256 + tid;            // 2048 float4s of B
            int kk = fidx >> 5, v4 = fidx & 31;
            float4 vB = *reinterpret_cast<const float4*>(
                &Wd[(size_t)(k0 + kk) * VV + v4 * 4]);
            *reinterpret_cast<float4*>(&Bsm[kk * 128 + v4 * 4]) = vB;
        }
        __syncthreads();

#pragma unroll 4
        for (int kk = 0; kk < 64; ++kk) {
            float a0 = Asm[m0 * 68 + kk];
            float a1 = Asm[(m0 + 1) * 68 + kk];
            float4 q0 = *reinterpret_cast<const float4*>(&Bsm[kk * 128 + n0]);
            float4 q1 = *reinterpret_cast<const float4*>(&Bsm[kk * 128 + n0 + 4]);
            acc[0][0] = fmaf(a0, q0.x, acc[0][0]);
            acc[0][1] = fmaf(a0, q0.y, acc[0][1]);
            acc[0][2] = fmaf(a0, q0.z, acc[0][2]);
            acc[0][3] = fmaf(a0, q0.w, acc[0][3]);
            acc[0][4] = fmaf(a0, q1.x, acc[0][4]);
            acc[0][5] = fmaf(a0, q1.y, acc[0][5]);
            acc[0][6] = fmaf(a0, q1.z, acc[0][6]);
            acc[0][7] = fmaf(a0, q1.w, acc[0][7]);
            acc[1][0] = fmaf(a1, q0.x, acc[1][0]);
            acc[1][1] = fmaf(a1, q0.y, acc[1][1]);
            acc[1][2] = fmaf(a1, q0.z, acc[1][2]);
            acc[1][3] = fmaf(a1, q0.w, acc[1][3]);
            acc[1][4] = fmaf(a1, q1.x, acc[1][4]);
            acc[1][5] = fmaf(a1, q1.y, acc[1][5]);
            acc[1][6] = fmaf(a1, q1.z, acc[1][6]);
            acc[1][7] = fmaf(a1, q1.w, acc[1][7]);
        }
    }

#pragma unroll
    for (int a = 0; a < 2; a++) {
        int m = m0 + a;
        float* op = &out[((size_t)m * TT + t) * VV + n0];
#pragma unroll
        for (int q = 0; q < 8; q++) op[q] = acc[a][q] + bd[n0 + q];
    }
}

// ------------------------------- launch --------------------------------------
extern "C" void kernel_launch(void* const* d_in, const int* in_sizes, int n_in,
                              void* d_out, int out_size) {
    (void)in_sizes; (void)n_in; (void)out_size;
    const int*   tokens = (const int*)  d_in[0];
    const float* emb    = (const float*)d_in[1];
    const float* Wk     = (const float*)d_in[2];
    const float* Uk     = (const float*)d_in[3];
    const float* b_in   = (const float*)d_in[4];
    const float* b_rec  = (const float*)d_in[5];
    const float* Wd     = (const float*)d_in[6];
    const float* bd     = (const float*)d_in[7];
    float* out = (float*)d_out;

    cudaFuncSetAttribute(k_recur, cudaFuncAttributeMaxDynamicSharedMemorySize, SMEM_RECUR);

    dim3 gin_grid(GG / 128, VV / 8);
    k_gin<<<gin_grid, 128>>>(emb, Wk, b_in);
    k_init<<<BB, TT>>>(tokens);
    k_recur<<<NC, RT, SMEM_RECUR>>>(Uk, b_rec);
    k_logits<<<TT, 256>>>(Wd, bd, out);
}